// round 10
// baseline (speedup 1.0000x reference)
#include <cuda_runtime.h>
#include <cuda_bf16.h>
#include <math.h>

// BidirectionalALiBi: out[h, i, j] = |j - i| * m
//   m = alpha[h] if (i==0 || j==0), gamma[h] if j>i, beta[h] if j<i.
//
// Linear-in-j form (i != 0):
//   upper (j >= i): v = fma(j,  g, -i*g)
//   lower (j <= i): v = fma(j, -b,  i*b)
//   row i==0:       v = j * a ;  col j==0, i>0: v = i * a
//
// R10: 4 rows per block (4 | S, so one head per block), 256 threads.
// Per thread: coefficients + fj loaded/computed once, then 4 independent
// (8x FMA -> STG.256.CS) groups -> store MLP 4, 4x fewer CTA prologues.

__global__ void __launch_bounds__(256, 8)
alibi_kernel(const float* __restrict__ alpha,
             const float* __restrict__ beta,
             const float* __restrict__ gamma,
             float* __restrict__ out,
             int S, int log2S)
{
    const int row0 = blockIdx.x << 2;          // first of 4 rows (same head)
    const int h = row0 >> log2S;
    const int i0 = row0 & (S - 1);

    const float a = __ldg(&alpha[h]);
    const float b = __ldg(&beta[h]);
    const float g = __ldg(&gamma[h]);

    const int j0 = threadIdx.x << 3;           // 8 elements per thread
    float fjv[8];
#pragma unroll
    for (int k = 0; k < 8; ++k) fjv[k] = (float)(j0 + k);

    float* base = out + (size_t)row0 * (size_t)S + j0;   // 32B-aligned

#pragma unroll
    for (int rr = 0; rr < 4; ++rr) {
        const int i = i0 + rr;
        const float fi = (float)i;

        float v[8];

        if (i == 0) {
#pragma unroll
            for (int k = 0; k < 8; ++k) v[k] = fjv[k] * a;
        } else if (j0 >= i) {                  // entirely upper (diag -> 0)
            const float c0 = -fi * g;
#pragma unroll
            for (int k = 0; k < 8; ++k) v[k] = fmaf(fjv[k], g, c0);
        } else if (j0 + 7 <= i) {              // entirely lower (diag -> 0)
            const float c0 = fi * b;
            const float nb = -b;
#pragma unroll
            for (int k = 0; k < 8; ++k) v[k] = fmaf(fjv[k], nb, c0);
        } else {                               // straddles diagonal (rare)
#pragma unroll
            for (int k = 0; k < 8; ++k) {
                const int j = j0 + k;
                const float m = (j > i) ? g : b;
                v[k] = fabsf((float)j - fi) * m;
            }
        }

        if (j0 == 0 && i != 0) v[0] = fi * a;  // edge column j==0

        float* p = base + (size_t)rr * (size_t)S;
        asm volatile(
            "st.global.cs.v8.b32 [%0], {%1,%2,%3,%4,%5,%6,%7,%8};"
            :: "l"(p),
               "r"(__float_as_uint(v[0])), "r"(__float_as_uint(v[1])),
               "r"(__float_as_uint(v[2])), "r"(__float_as_uint(v[3])),
               "r"(__float_as_uint(v[4])), "r"(__float_as_uint(v[5])),
               "r"(__float_as_uint(v[6])), "r"(__float_as_uint(v[7]))
            : "memory");
    }
}

extern "C" void kernel_launch(void* const* d_in, const int* in_sizes, int n_in,
                              void* d_out, int out_size)
{
    const float* alpha = (const float*)d_in[0];
    const float* beta  = (const float*)d_in[1];
    const float* gamma = (const float*)d_in[2];
    float* out = (float*)d_out;

    const int H = in_sizes[0];                 // 16
    long long ss = (long long)out_size / H;    // S*S
    int S = (int)(sqrt((double)ss) + 0.5);

    int log2S = 0;
    while ((1 << log2S) < S) ++log2S;          // S is a power of two (2048)

    const int threads = 256;                   // 8 floats/thread -> one row
    const int blocks = (H * S) >> 2;           // 4 rows per block

    alibi_kernel<<<blocks, threads>>>(alpha, beta, gamma, out, S, log2S);
}

// round 11
// speedup vs baseline: 1.0031x; 1.0031x over previous
#include <cuda_runtime.h>
#include <cuda_bf16.h>
#include <math.h>

// BidirectionalALiBi: out[h, i, j] = |j - i| * m
//   m = alpha[h] if (i==0 || j==0), gamma[h] if j>i, beta[h] if j<i.
//
// Branchless exact form:
//   cu = (i==0) ? a : g            (row-uniform)
//   c1(j) = (j > i) ? cu : -b      (per element)
//   v(j)  = (j - i) * c1 = fma(fj, c1, -fi*c1)
// Checks: j>i -> (j-i)*g (or (j-0)*a when i==0) ; j<i -> (j-i)*(-b)=(i-j)*b ;
// j==i -> 0 ; i==0,j==0 -> 0. Only fixup: j==0 && i>0 -> i*a.
//
// Geometry: best-measured config — one block per row, 256 threads, one
// 256-bit streaming store per thread (st.global.cs.v8.b32), warp = 1KB
// contiguous. DRAM write ceiling (~5.6 TB/s) is the binding limit.

__global__ void __launch_bounds__(256, 8)
alibi_kernel(const float* __restrict__ alpha,
             const float* __restrict__ beta,
             const float* __restrict__ gamma,
             float* __restrict__ out,
             int S, int log2S)
{
    const int row = blockIdx.x;            // row = h * S + i
    const int h = row >> log2S;
    const int i = row & (S - 1);

    const float a = __ldg(&alpha[h]);
    const float b = __ldg(&beta[h]);
    const float g = __ldg(&gamma[h]);

    const float fi = (float)i;
    const float cu = (i == 0) ? a : g;     // upper coefficient (row-uniform)
    const float cl = -b;                   // lower coefficient

    const int j0 = threadIdx.x << 3;       // 8 elements per thread

    float v[8];
#pragma unroll
    for (int k = 0; k < 8; ++k) {
        const int j = j0 + k;
        const float c1 = (j > i) ? cu : cl;
        const float fj = (float)j;
        v[k] = fmaf(fj, c1, -fi * c1);     // (j - i) * c1
    }

    if (j0 == 0 && i != 0) v[0] = fi * a;  // edge column j==0

    float* p = out + (size_t)row * (size_t)S + j0;   // 32B-aligned
    asm volatile(
        "st.global.cs.v8.b32 [%0], {%1,%2,%3,%4,%5,%6,%7,%8};"
        :: "l"(p),
           "r"(__float_as_uint(v[0])), "r"(__float_as_uint(v[1])),
           "r"(__float_as_uint(v[2])), "r"(__float_as_uint(v[3])),
           "r"(__float_as_uint(v[4])), "r"(__float_as_uint(v[5])),
           "r"(__float_as_uint(v[6])), "r"(__float_as_uint(v[7]))
        : "memory");
}

extern "C" void kernel_launch(void* const* d_in, const int* in_sizes, int n_in,
                              void* d_out, int out_size)
{
    const float* alpha = (const float*)d_in[0];
    const float* beta  = (const float*)d_in[1];
    const float* gamma = (const float*)d_in[2];
    float* out = (float*)d_out;

    const int H = in_sizes[0];                 // 16
    long long ss = (long long)out_size / H;    // S*S
    int S = (int)(sqrt((double)ss) + 0.5);

    int log2S = 0;
    while ((1 << log2S) < S) ++log2S;          // S is a power of two (2048)

    const int threads = 256;                   // 8 floats/thread -> 2048 cols
    const int blocks = H * S;                  // one block per row

    alibi_kernel<<<blocks, threads>>>(alpha, beta, gamma, out, S, log2S);
}

// round 12
// speedup vs baseline: 1.0166x; 1.0135x over previous
#include <cuda_runtime.h>
#include <cuda_bf16.h>
#include <math.h>

// BidirectionalALiBi: out[h, i, j] = |j - i| * m
//   m = alpha[h] if (i==0 || j==0), gamma[h] if j>i, beta[h] if j<i.
//
// Linear-in-j form (i != 0):
//   upper (j >= i): v = fma(j,  g, -i*g)
//   lower (j <= i): v = fma(j, -b,  i*b)
//   row i==0:       v = j * a ;  col j==0, i>0: v = i * a
//
// FINAL (best measured, replicated 3x at 39.4us): one block per row,
// 256 threads, 8 consecutive floats per thread, one 256-bit streaming
// store (st.global.cs.v8.b32) per thread — warp covers 1KB contiguous.
// Coefficients hoisted per thread; only the single diagonal-straddling
// thread per row takes the per-element path.
//
// Measured invariant across 10 variants: DRAM pinned at 70+-1% (~5.6TB/s)
// regardless of issue/occupancy/MLP/store policy — HBM write-drain ceiling.

__global__ void __launch_bounds__(256, 8)
alibi_kernel(const float* __restrict__ alpha,
             const float* __restrict__ beta,
             const float* __restrict__ gamma,
             float* __restrict__ out,
             int S, int log2S)
{
    const int row = blockIdx.x;            // row = h * S + i
    const int h = row >> log2S;
    const int i = row - (h << log2S);

    const float a = __ldg(&alpha[h]);
    const float b = __ldg(&beta[h]);
    const float g = __ldg(&gamma[h]);
    const float fi = (float)i;

    const int j0 = threadIdx.x << 3;       // 8 elements per thread
    const float fj = (float)j0;

    float v[8];

    if (i == 0) {
#pragma unroll
        for (int k = 0; k < 8; ++k) v[k] = (fj + (float)k) * a;
    } else if (j0 >= i) {                  // entirely upper (diag -> 0)
        const float c0 = -fi * g;
#pragma unroll
        for (int k = 0; k < 8; ++k) v[k] = fmaf(fj + (float)k, g, c0);
    } else if (j0 + 7 <= i) {              // entirely lower (diag -> 0)
        const float c0 = fi * b;
        const float nb = -b;
#pragma unroll
        for (int k = 0; k < 8; ++k) v[k] = fmaf(fj + (float)k, nb, c0);
    } else {                               // straddles diagonal (1 thread/row)
#pragma unroll
        for (int k = 0; k < 8; ++k) {
            const int j = j0 + k;
            const float m = (j > i) ? g : b;
            v[k] = fabsf((float)j - fi) * m;
        }
    }

    if (j0 == 0 && i != 0) v[0] = fi * a;  // edge column j==0

    float* p = out + (size_t)row * (size_t)S + j0;   // 32B-aligned
    asm volatile(
        "st.global.cs.v8.b32 [%0], {%1, %2, %3, %4, %5, %6, %7, %8};"
        :: "l"(p),
           "r"(__float_as_uint(v[0])), "r"(__float_as_uint(v[1])),
           "r"(__float_as_uint(v[2])), "r"(__float_as_uint(v[3])),
           "r"(__float_as_uint(v[4])), "r"(__float_as_uint(v[5])),
           "r"(__float_as_uint(v[6])), "r"(__float_as_uint(v[7]))
        : "memory");
}

extern "C" void kernel_launch(void* const* d_in, const int* in_sizes, int n_in,
                              void* d_out, int out_size)
{
    const float* alpha = (const float*)d_in[0];
    const float* beta  = (const float*)d_in[1];
    const float* gamma = (const float*)d_in[2];
    float* out = (float*)d_out;

    const int H = in_sizes[0];                 // 16
    long long ss = (long long)out_size / H;    // S*S
    int S = (int)(sqrt((double)ss) + 0.5);

    int log2S = 0;
    while ((1 << log2S) < S) ++log2S;          // S is a power of two (2048)

    const int threads = 256;                   // 8 floats per thread -> 2048 cols
    const int blocks = H * S;                  // one block per row

    alibi_kernel<<<blocks, threads>>>(alpha, beta, gamma, out, S, log2S);
}